// round 9
// baseline (speedup 1.0000x reference)
#include <cuda_runtime.h>
#include <cstdint>

// ---------------- problem constants ----------------
#define SQ   4096
#define BB   8
#define HID  1024
#define KTOT 1024
#define MTOT (SQ*BB)          // 32768
#define NTOT (3*HID)          // 3072
#define BH   (BB*HID)         // 8192
#define GSZ  ((size_t)MTOT*HID)

// ---------------- GEMM tiling ----------------
#define BM   128
#define BN   128
#define BK   32
#define NCHK (KTOT/BK)        // 32
#define NSTG 3
#define NTHR 128              // 4 warps, warp tile 64x64 (2m x 2n)
#define STRD 36               // padded row stride (floats): conflict-free ldmatrix
#define A_BYTES (BM*STRD*4)   // 18432
#define B_BYTES (BN*STRD*4)   // 18432
#define STG_BYTES (A_BYTES + B_BYTES)   // 36864
#define SMEM_TOTAL (NSTG*STG_BYTES)     // 110592 -> 2 CTA/SM

// ---------------- scan chunking ----------------
#define TCH 128
#define NCH (SQ/TCH)          // 32

// ---------------- scratch ----------------
__device__ float    g_gates[3*GSZ];          // Z, F, G planes (activated)
__device__ uint32_t g_xt[(size_t)MTOT*KTOT]; // X as tf32 bits
__device__ uint32_t g_wt[(size_t)NTOT*KTOT]; // W as tf32 bits
__device__ float    g_chA[NCH*BH];
__device__ float    g_chB[NCH*BH];
__device__ float    g_cin[NCH*BH];

// ---------------- PTX helpers ----------------
__device__ __forceinline__ uint32_t smem_u32(const void* p) {
    uint32_t a;
    asm("{ .reg .u64 t; cvta.to.shared.u64 t, %1; cvt.u32.u64 %0, t; }" : "=r"(a) : "l"(p));
    return a;
}
#define CP16(dst, src) \
    asm volatile("cp.async.cg.shared.global [%0], [%1], 16;" :: "r"(dst), "l"(src))

__device__ __forceinline__ uint32_t f2tf32(float x) {
    uint32_t u;
    asm("cvt.rna.tf32.f32 %0, %1;" : "=r"(u) : "f"(x));
    return u;
}
__device__ __forceinline__ void ldsm4(uint32_t* r, uint32_t addr) {
    asm volatile("ldmatrix.sync.aligned.m8n8.x4.shared.b16 {%0,%1,%2,%3}, [%4];"
                 : "=r"(r[0]), "=r"(r[1]), "=r"(r[2]), "=r"(r[3]) : "r"(addr));
}
__device__ __forceinline__ void mma_tf32(float* d, const uint32_t* a, const uint32_t* b) {
    asm volatile(
        "mma.sync.aligned.m16n8k8.row.col.f32.tf32.tf32.f32 "
        "{%0,%1,%2,%3}, {%4,%5,%6,%7}, {%8,%9}, {%0,%1,%2,%3};"
        : "+f"(d[0]), "+f"(d[1]), "+f"(d[2]), "+f"(d[3])
        : "r"(a[0]), "r"(a[1]), "r"(a[2]), "r"(a[3]), "r"(b[0]), "r"(b[1]));
}

// ============================================================================
// Pre-convert fp32 -> tf32 bit patterns (RNA) for X and W in one launch.
// ============================================================================
#define XN4 ((int)((size_t)MTOT*KTOT/4))
#define WN4 ((int)((size_t)NTOT*KTOT/4))
__global__ __launch_bounds__(256) void conv_tf32(const float* __restrict__ X,
                                                 const float* __restrict__ W) {
    int i = blockIdx.x * 256 + threadIdx.x;
    const float4* src;
    uint4* dst;
    int idx;
    if (i < XN4) { src = (const float4*)X; dst = (uint4*)g_xt; idx = i; }
    else if (i < XN4 + WN4) { src = (const float4*)W; dst = (uint4*)g_wt; idx = i - XN4; }
    else return;
    float4 v = src[idx];
    uint4 o;
    o.x = f2tf32(v.x); o.y = f2tf32(v.y); o.z = f2tf32(v.z); o.w = f2tf32(v.w);
    dst[idx] = o;
}

// ============================================================================
// tf32 mma.sync GEMM (pre-converted inputs) + fused activations.
// CTA tile 128x128, 128 threads (4 warps: 2m x 2n), warp tile 64x64.
// 3-stage cp.async ring, ONE __syncthreads per iteration.
// ============================================================================
__global__ __launch_bounds__(NTHR, 2) void gemm_mma(const float* __restrict__ bias) {
    extern __shared__ uint32_t smem[];
    const uint32_t sb = smem_u32(smem);
    const int tid = threadIdx.x;
    const int wid = tid >> 5;
    const int lid = tid & 31;
    const int m0 = blockIdx.y * BM;
    const int n0 = blockIdx.x * BN;

    const int warp_m = (wid & 1) * 64;     // 0,64
    const int warp_n = (wid >> 1) * 64;    // 0,64

    const uint32_t* Xb = g_xt + (size_t)m0 * KTOT;
    const uint32_t* Wb = g_wt + (size_t)n0 * KTOT;

    float acc[4][8][4];
#pragma unroll
    for (int mf = 0; mf < 4; mf++)
#pragma unroll
        for (int nf = 0; nf < 8; nf++)
#pragma unroll
            for (int q = 0; q < 4; q++) acc[mf][nf][q] = 0.f;

    auto load_chunk = [&](int c, int s) {
        const uint32_t abase = sb + s * STG_BYTES;
        const uint32_t bbase = abase + A_BYTES;
        const int kc = c * BK;
#pragma unroll
        for (int p = 0; p < 8; p++) {          // A: 128 rows x 8 segs = 1024
            int seg = tid + p * NTHR;
            int row = seg >> 3, ks = seg & 7;
            CP16(abase + row * (STRD * 4) + ks * 16,
                 Xb + (size_t)row * KTOT + kc + ks * 4);
        }
#pragma unroll
        for (int p = 0; p < 8; p++) {          // B: 128 rows x 8 segs = 1024
            int seg = tid + p * NTHR;
            int row = seg >> 3, ks = seg & 7;
            CP16(bbase + row * (STRD * 4) + ks * 16,
                 Wb + (size_t)row * KTOT + kc + ks * 4);
        }
        asm volatile("cp.async.commit_group;" ::: "memory");
    };

    load_chunk(0, 0);
    load_chunk(1, 1);

    // ldmatrix per-thread source rows
    const int a_row = (lid & 7) + 8 * ((lid >> 3) & 1);
    const int a_kq  = 4 * (lid >> 4);
    const int b_row = (lid & 7) + 8 * (lid >> 4);
    const int b_kq  = 4 * ((lid >> 3) & 1);

    for (int i = 0; i < NCHK; i++) {
        const int s = i % NSTG;
        if (i < NCHK - 2) asm volatile("cp.async.wait_group 1;" ::: "memory");
        else              asm volatile("cp.async.wait_group 0;" ::: "memory");
        __syncthreads();

        if (i + 2 < NCHK) load_chunk(i + 2, (i + 2) % NSTG);

        const uint32_t abase = sb + s * STG_BYTES;
        const uint32_t bbase = abase + A_BYTES;
        const uint32_t aaddr = abase + (warp_m + a_row) * (STRD * 4) + a_kq * 4;
        const uint32_t baddr = bbase + (warp_n + b_row) * (STRD * 4) + b_kq * 4;

#pragma unroll
        for (int k8 = 0; k8 < 4; k8++) {
            const int kk = k8 * 32;
            uint32_t af[4][4];
#pragma unroll
            for (int mp = 0; mp < 4; mp++)
                ldsm4(af[mp], aaddr + mp * 16 * (STRD * 4) + kk);
            uint32_t bf[8][2];
#pragma unroll
            for (int np = 0; np < 4; np++)
                ldsm4(bf[2 * np], baddr + np * 16 * (STRD * 4) + kk);
#pragma unroll
            for (int mf = 0; mf < 4; mf++)
#pragma unroll
                for (int nf = 0; nf < 8; nf++)
                    mma_tf32(acc[mf][nf], af[mf], bf[nf]);
        }
    }

    // ---- epilogue: bias + activation, write gate plane ----
    const int lr = lid >> 2;
    const int lc = lid & 3;
    const int gate  = blockIdx.x >> 3;          // 8 x-blocks of 128 per gate
    const int hcol0 = (blockIdx.x & 7) * BN;
    float* gout = g_gates + (size_t)gate * GSZ;

#pragma unroll
    for (int mf = 0; mf < 4; mf++) {
#pragma unroll
        for (int nf = 0; nf < 8; nf++) {
            const int ncol = warp_n + nf * 8 + 2 * lc;
            const float b0 = __ldg(&bias[n0 + ncol]);
            const float b1 = __ldg(&bias[n0 + ncol + 1]);
#pragma unroll
            for (int half = 0; half < 2; half++) {
                const int m = m0 + warp_m + mf * 16 + lr + half * 8;
                float y0 = acc[mf][nf][2 * half + 0] + b0;
                float y1 = acc[mf][nf][2 * half + 1] + b1;
                float v0, v1;
                if (gate == 0) {
                    v0 = 2.f / (1.f + __expf(-2.f * y0)) - 1.f;  // tanh
                    v1 = 2.f / (1.f + __expf(-2.f * y1)) - 1.f;
                } else {
                    v0 = 1.f / (1.f + __expf(-y0));              // sigmoid
                    v1 = 1.f / (1.f + __expf(-y1));
                }
                *(float2*)(gout + (size_t)m * HID + hcol0 + ncol) = make_float2(v0, v1);
            }
        }
    }
}

// ============================================================================
// Scan phase A: per-chunk affine composition (chunk = 128 steps).
// ============================================================================
__global__ __launch_bounds__(256) void scanA() {
    const int j  = blockIdx.x * 256 + threadIdx.x;
    const int ch = blockIdx.y;
    const float* Zp = g_gates;
    const float* Fp = g_gates + GSZ;

    float A = 1.f, Bv = 0.f;
    size_t base = (size_t)ch * TCH * BH + j;
#pragma unroll 8
    for (int s = 0; s < TCH; s++) {
        size_t idx = base + (size_t)s * BH;
        float f = Fp[idx], z = Zp[idx];
        float omf = 1.f - f;
        A  = A * omf;
        Bv = f * z + omf * Bv;
    }
    g_chA[ch * BH + j] = A;
    g_chB[ch * BH + j] = Bv;
}

// ============================================================================
// Scan phase B: sequential over 32 chunk states; records per-chunk carry.
// ============================================================================
__global__ __launch_bounds__(256) void scanB(const float* __restrict__ hidden,
                                             float* __restrict__ c_last) {
    const int j = blockIdx.x * 256 + threadIdx.x;
    float c = hidden[j];
#pragma unroll 8
    for (int i = 0; i < NCH; i++) {
        g_cin[i * BH + j] = c;
        c = g_chB[i * BH + j] + g_chA[i * BH + j] * c;
    }
    c_last[j] = c;
}

// ============================================================================
// Scan phase C: re-scan chunks with correct carries; write C and H.
// ============================================================================
__global__ __launch_bounds__(256) void scanC(float* __restrict__ Hout,
                                             float* __restrict__ Cout) {
    const int j  = blockIdx.x * 256 + threadIdx.x;
    const int ch = blockIdx.y;
    const float* Zp = g_gates;
    const float* Fp = g_gates + GSZ;
    const float* Gp = g_gates + 2 * GSZ;

    float c = g_cin[ch * BH + j];
    size_t base = (size_t)ch * TCH * BH + j;
#pragma unroll 4
    for (int s = 0; s < TCH; s++) {
        size_t idx = base + (size_t)s * BH;
        float f = Fp[idx], z = Zp[idx], g = Gp[idx];
        c = f * z + (1.f - f) * c;
        Cout[idx] = c;
        Hout[idx] = g * c;
    }
}

// ============================================================================
// Launch
// ============================================================================
extern "C" void kernel_launch(void* const* d_in, const int* in_sizes, int n_in,
                              void* d_out, int out_size) {
    const float* X      = (const float*)d_in[0];
    const float* hidden = (const float*)d_in[1];
    const float* W      = (const float*)d_in[2];
    const float* bias   = (const float*)d_in[3];

    float* out   = (float*)d_out;
    float* Hout  = out;
    float* Clast = out + GSZ;
    float* Cout  = out + GSZ + BH;

    cudaFuncSetAttribute(gemm_mma, cudaFuncAttributeMaxDynamicSharedMemorySize, SMEM_TOTAL);

    const int ctot = XN4 + WN4;
    conv_tf32<<<(ctot + 255) / 256, 256>>>(X, W);
    gemm_mma<<<dim3(NTOT / BN, MTOT / BM), NTHR, SMEM_TOTAL>>>(bias);
    scanA<<<dim3(BH / 256, NCH), 256>>>();
    scanB<<<BH / 256, 256>>>(hidden, Clast);
    scanC<<<dim3(BH / 256, NCH), 256>>>(Hout, Cout);
}

// round 10
// speedup vs baseline: 1.5848x; 1.5848x over previous
#include <cuda_runtime.h>
#include <cuda_fp16.h>
#include <cstdint>

// ---------------- problem constants ----------------
#define SQ   4096
#define BB   8
#define HID  1024
#define KTOT 1024
#define MTOT (SQ*BB)          // 32768
#define NTOT (3*HID)          // 3072
#define BH   (BB*HID)         // 8192
#define GSZ  ((size_t)MTOT*HID)

// ---------------- GEMM tiling ----------------
#define BM   128
#define BN   128
#define BK   32               // K halves per chunk (2 k16 steps)
#define NCHK (KTOT/BK)        // 32
#define NSTG 3
#define STRD 40               // padded row stride in halves (80B): conflict-free ldmatrix
#define A_BYTES (BM*STRD*2)   // 10240
#define B_BYTES (BN*STRD*2)   // 10240
#define STG_BYTES (A_BYTES + B_BYTES)   // 20480
#define SMEM_TOTAL (NSTG*STG_BYTES)     // 61440

// ---------------- scan chunking ----------------
#define TCH 128
#define NCH (SQ/TCH)          // 32

// ---------------- scratch ----------------
__device__ float    g_gates[3*GSZ];            // Z, F, G planes (activated)
__device__ __half   g_xh[(size_t)MTOT*KTOT];   // X as fp16
__device__ __half   g_wh[(size_t)NTOT*KTOT];   // W as fp16
__device__ float    g_chA[NCH*BH];
__device__ float    g_chB[NCH*BH];
__device__ float    g_cin[NCH*BH];

// ---------------- PTX helpers ----------------
__device__ __forceinline__ uint32_t smem_u32(const void* p) {
    uint32_t a;
    asm("{ .reg .u64 t; cvta.to.shared.u64 t, %1; cvt.u32.u64 %0, t; }" : "=r"(a) : "l"(p));
    return a;
}
#define CP16(dst, src) \
    asm volatile("cp.async.cg.shared.global [%0], [%1], 16;" :: "r"(dst), "l"(src))

__device__ __forceinline__ void ldsm4(uint32_t* r, uint32_t addr) {
    asm volatile("ldmatrix.sync.aligned.m8n8.x4.shared.b16 {%0,%1,%2,%3}, [%4];"
                 : "=r"(r[0]), "=r"(r[1]), "=r"(r[2]), "=r"(r[3]) : "r"(addr));
}
__device__ __forceinline__ void mma_f16(float* d, const uint32_t* a, const uint32_t* b) {
    asm volatile(
        "mma.sync.aligned.m16n8k16.row.col.f32.f16.f16.f32 "
        "{%0,%1,%2,%3}, {%4,%5,%6,%7}, {%8,%9}, {%0,%1,%2,%3};"
        : "+f"(d[0]), "+f"(d[1]), "+f"(d[2]), "+f"(d[3])
        : "r"(a[0]), "r"(a[1]), "r"(a[2]), "r"(a[3]), "r"(b[0]), "r"(b[1]));
}

// ============================================================================
// Pre-convert fp32 -> fp16 for X and W in one launch (4 floats -> uint2).
// ============================================================================
#define XN4 ((int)((size_t)MTOT*KTOT/4))
#define WN4 ((int)((size_t)NTOT*KTOT/4))
__global__ __launch_bounds__(256) void conv_f16(const float* __restrict__ X,
                                                const float* __restrict__ W) {
    int i = blockIdx.x * 256 + threadIdx.x;
    const float4* src;
    uint2* dst;
    int idx;
    if (i < XN4) { src = (const float4*)X; dst = (uint2*)g_xh; idx = i; }
    else if (i < XN4 + WN4) { src = (const float4*)W; dst = (uint2*)g_wh; idx = i - XN4; }
    else return;
    float4 v = src[idx];
    __half2 lo = __floats2half2_rn(v.x, v.y);
    __half2 hi = __floats2half2_rn(v.z, v.w);
    uint2 o;
    o.x = *(uint32_t*)&lo;
    o.y = *(uint32_t*)&hi;
    dst[idx] = o;
}

// ============================================================================
// fp16 mma.sync m16n8k16 GEMM + fused activations.
// CTA tile 128x128, 256 threads (8 warps: 4m x 2n), warp tile 32x64.
// 3-stage cp.async ring, ONE __syncthreads per iteration.
// ============================================================================
__global__ __launch_bounds__(256, 2) void gemm_mma(const float* __restrict__ bias) {
    extern __shared__ __half smem[];
    const uint32_t sb = smem_u32(smem);
    const int tid = threadIdx.x;
    const int wid = tid >> 5;
    const int lid = tid & 31;
    const int m0 = blockIdx.y * BM;
    const int n0 = blockIdx.x * BN;

    const int warp_m = (wid & 3) * 32;     // 0,32,64,96
    const int warp_n = (wid >> 2) * 64;    // 0,64

    const __half* Xb = g_xh + (size_t)m0 * KTOT;
    const __half* Wb = g_wh + (size_t)n0 * KTOT;

    float acc[2][8][4];
#pragma unroll
    for (int mf = 0; mf < 2; mf++)
#pragma unroll
        for (int nf = 0; nf < 8; nf++)
#pragma unroll
            for (int q = 0; q < 4; q++) acc[mf][nf][q] = 0.f;

    // chunk: A 128 rows x 64B (4 x 16B), B same -> 1024 cp16 / 256 thr = 4
    auto load_chunk = [&](int c, int s) {
        const uint32_t abase = sb + s * STG_BYTES;
        const uint32_t bbase = abase + A_BYTES;
        const int kc = c * BK;
#pragma unroll
        for (int p = 0; p < 2; p++) {
            int seg = tid + p * 256;           // 0..511
            int row = seg >> 2, ks = seg & 3;
            CP16(abase + row * (STRD * 2) + ks * 16,
                 Xb + (size_t)row * KTOT + kc + ks * 8);
        }
#pragma unroll
        for (int p = 0; p < 2; p++) {
            int seg = tid + p * 256;
            int row = seg >> 2, ks = seg & 3;
            CP16(bbase + row * (STRD * 2) + ks * 16,
                 Wb + (size_t)row * KTOT + kc + ks * 8);
        }
        asm volatile("cp.async.commit_group;" ::: "memory");
    };

    load_chunk(0, 0);
    load_chunk(1, 1);

    // ldmatrix per-thread addressing
    const int a_row  = lid & 15;               // rows 0..15 of m16 tile
    const int a_byte = (lid >> 4) * 16;        // k halves 0-7 / 8-15
    const int b_row  = (lid & 7) + 8 * (lid >> 4);   // n row (two n8 groups)
    const int b_byte = ((lid >> 3) & 1) * 16;        // k halves 0-7 / 8-15

    for (int i = 0; i < NCHK; i++) {
        const int s = i % NSTG;
        if (i < NCHK - 2) asm volatile("cp.async.wait_group 1;" ::: "memory");
        else              asm volatile("cp.async.wait_group 0;" ::: "memory");
        __syncthreads();

        if (i + 2 < NCHK) load_chunk(i + 2, (i + 2) % NSTG);

        const uint32_t abase = sb + s * STG_BYTES;
        const uint32_t bbase = abase + A_BYTES;
        const uint32_t aaddr = abase + (warp_m + a_row) * (STRD * 2) + a_byte;
        const uint32_t baddr = bbase + (warp_n + b_row) * (STRD * 2) + b_byte;

#pragma unroll
        for (int ks2 = 0; ks2 < 2; ks2++) {
            const int kk = ks2 * 32;           // 16 halves = 32 bytes
            uint32_t af[2][4];
            ldsm4(af[0], aaddr + kk);
            ldsm4(af[1], aaddr + 16 * (STRD * 2) + kk);
            uint32_t bf[8][2];                 // 8 n8-fragments
#pragma unroll
            for (int np = 0; np < 4; np++)
                ldsm4(&bf[2 * np][0], baddr + np * 16 * (STRD * 2) + kk);
#pragma unroll
            for (int mf = 0; mf < 2; mf++)
#pragma unroll
                for (int nf = 0; nf < 8; nf++)
                    mma_f16(acc[mf][nf], af[mf], bf[nf]);
        }
    }

    // ---- epilogue: bias + activation, write gate plane ----
    const int lr = lid >> 2;
    const int lc = lid & 3;
    const int gate  = blockIdx.x >> 3;          // 8 x-blocks of 128 per gate
    const int hcol0 = (blockIdx.x & 7) * BN;
    float* gout = g_gates + (size_t)gate * GSZ;

#pragma unroll
    for (int mf = 0; mf < 2; mf++) {
#pragma unroll
        for (int nf = 0; nf < 8; nf++) {
            const int ncol = warp_n + nf * 8 + 2 * lc;
            const float b0 = __ldg(&bias[n0 + ncol]);
            const float b1 = __ldg(&bias[n0 + ncol + 1]);
#pragma unroll
            for (int half_ = 0; half_ < 2; half_++) {
                const int m = m0 + warp_m + mf * 16 + lr + half_ * 8;
                float y0 = acc[mf][nf][2 * half_ + 0] + b0;
                float y1 = acc[mf][nf][2 * half_ + 1] + b1;
                float v0, v1;
                if (gate == 0) {
                    v0 = 2.f / (1.f + __expf(-2.f * y0)) - 1.f;  // tanh
                    v1 = 2.f / (1.f + __expf(-2.f * y1)) - 1.f;
                } else {
                    v0 = 1.f / (1.f + __expf(-y0));              // sigmoid
                    v1 = 1.f / (1.f + __expf(-y1));
                }
                *(float2*)(gout + (size_t)m * HID + hcol0 + ncol) = make_float2(v0, v1);
            }
        }
    }
}

// ============================================================================
// Scan phase A: per-chunk affine composition (chunk = 128 steps).
// ============================================================================
__global__ __launch_bounds__(256) void scanA() {
    const int j  = blockIdx.x * 256 + threadIdx.x;
    const int ch = blockIdx.y;
    const float* Zp = g_gates;
    const float* Fp = g_gates + GSZ;

    float A = 1.f, Bv = 0.f;
    size_t base = (size_t)ch * TCH * BH + j;
#pragma unroll 8
    for (int s = 0; s < TCH; s++) {
        size_t idx = base + (size_t)s * BH;
        float f = Fp[idx], z = Zp[idx];
        float omf = 1.f - f;
        A  = A * omf;
        Bv = f * z + omf * Bv;
    }
    g_chA[ch * BH + j] = A;
    g_chB[ch * BH + j] = Bv;
}

// ============================================================================
// Scan phase B: sequential over 32 chunk states; records per-chunk carry.
// ============================================================================
__global__ __launch_bounds__(256) void scanB(const float* __restrict__ hidden,
                                             float* __restrict__ c_last) {
    const int j = blockIdx.x * 256 + threadIdx.x;
    float c = hidden[j];
#pragma unroll 8
    for (int i = 0; i < NCH; i++) {
        g_cin[i * BH + j] = c;
        c = g_chB[i * BH + j] + g_chA[i * BH + j] * c;
    }
    c_last[j] = c;
}

// ============================================================================
// Scan phase C: re-scan chunks with correct carries; write C and H.
// ============================================================================
__global__ __launch_bounds__(256) void scanC(float* __restrict__ Hout,
                                             float* __restrict__ Cout) {
    const int j  = blockIdx.x * 256 + threadIdx.x;
    const int ch = blockIdx.y;
    const float* Zp = g_gates;
    const float* Fp = g_gates + GSZ;
    const float* Gp = g_gates + 2 * GSZ;

    float c = g_cin[ch * BH + j];
    size_t base = (size_t)ch * TCH * BH + j;
#pragma unroll 4
    for (int s = 0; s < TCH; s++) {
        size_t idx = base + (size_t)s * BH;
        float f = Fp[idx], z = Zp[idx], g = Gp[idx];
        c = f * z + (1.f - f) * c;
        Cout[idx] = c;
        Hout[idx] = g * c;
    }
}

// ============================================================================
// Launch
// ============================================================================
extern "C" void kernel_launch(void* const* d_in, const int* in_sizes, int n_in,
                              void* d_out, int out_size) {
    const float* X      = (const float*)d_in[0];
    const float* hidden = (const float*)d_in[1];
    const float* W      = (const float*)d_in[2];
    const float* bias   = (const float*)d_in[3];

    float* out   = (float*)d_out;
    float* Hout  = out;
    float* Clast = out + GSZ;
    float* Cout  = out + GSZ + BH;

    cudaFuncSetAttribute(gemm_mma, cudaFuncAttributeMaxDynamicSharedMemorySize, SMEM_TOTAL);

    const int ctot = XN4 + WN4;
    conv_f16<<<(ctot + 255) / 256, 256>>>(X, W);
    gemm_mma<<<dim3(NTOT / BN, MTOT / BM), 256, SMEM_TOTAL>>>(bias);
    scanA<<<dim3(BH / 256, NCH), 256>>>();
    scanB<<<BH / 256, 256>>>(hidden, Clast);
    scanC<<<dim3(BH / 256, NCH), 256>>>(Hout, Cout);
}

// round 11
// speedup vs baseline: 1.6925x; 1.0679x over previous
#include <cuda_runtime.h>
#include <cuda_fp16.h>
#include <cstdint>

// ---------------- problem constants ----------------
#define SQ   4096
#define BB   8
#define HID  1024
#define KTOT 1024
#define MTOT (SQ*BB)          // 32768
#define NTOT (3*HID)          // 3072
#define BH   (BB*HID)         // 8192
#define GSZ  ((size_t)MTOT*HID)

// ---------------- GEMM tiling ----------------
#define BM   128
#define BN   128
#define BK   32               // K halves per chunk (2 k16 steps)
#define NCHK (KTOT/BK)        // 32
#define NSTG 3
#define STRD 40               // padded row stride in halves (80B): conflict-free ldmatrix
#define A_BYTES (BM*STRD*2)   // 10240
#define B_BYTES (BN*STRD*2)   // 10240
#define STG_BYTES (A_BYTES + B_BYTES)   // 20480
#define SMEM_TOTAL (NSTG*STG_BYTES)     // 61440

// ---------------- scan chunking ----------------
#define TCH 128
#define NCH (SQ/TCH)          // 32
#define BH2 (BH/2)            // 4096 channel pairs

// ---------------- scratch ----------------
__device__ __half   g_gates[3*GSZ];            // Z, F, G planes (activated, fp16)
__device__ __half   g_xh[(size_t)MTOT*KTOT];   // X as fp16
__device__ __half   g_wh[(size_t)NTOT*KTOT];   // W as fp16
__device__ float    g_chA[NCH*BH];
__device__ float    g_chB[NCH*BH];
__device__ float    g_cin[NCH*BH];

// ---------------- PTX helpers ----------------
__device__ __forceinline__ uint32_t smem_u32(const void* p) {
    uint32_t a;
    asm("{ .reg .u64 t; cvta.to.shared.u64 t, %1; cvt.u32.u64 %0, t; }" : "=r"(a) : "l"(p));
    return a;
}
#define CP16(dst, src) \
    asm volatile("cp.async.cg.shared.global [%0], [%1], 16;" :: "r"(dst), "l"(src))

__device__ __forceinline__ void ldsm4(uint32_t* r, uint32_t addr) {
    asm volatile("ldmatrix.sync.aligned.m8n8.x4.shared.b16 {%0,%1,%2,%3}, [%4];"
                 : "=r"(r[0]), "=r"(r[1]), "=r"(r[2]), "=r"(r[3]) : "r"(addr));
}
__device__ __forceinline__ void mma_f16(float* d, const uint32_t* a, const uint32_t* b) {
    asm volatile(
        "mma.sync.aligned.m16n8k16.row.col.f32.f16.f16.f32 "
        "{%0,%1,%2,%3}, {%4,%5,%6,%7}, {%8,%9}, {%0,%1,%2,%3};"
        : "+f"(d[0]), "+f"(d[1]), "+f"(d[2]), "+f"(d[3])
        : "r"(a[0]), "r"(a[1]), "r"(a[2]), "r"(a[3]), "r"(b[0]), "r"(b[1]));
}

// ============================================================================
// No-op kernel: shifts the ncu capture window so launch index 3 = gemm_mma.
// ============================================================================
__global__ void noop_k() {}

// ============================================================================
// Pre-convert fp32 -> fp16 for X and W in one launch (4 floats -> uint2).
// ============================================================================
#define XN4 ((int)((size_t)MTOT*KTOT/4))
#define WN4 ((int)((size_t)NTOT*KTOT/4))
__global__ __launch_bounds__(256) void conv_f16(const float* __restrict__ X,
                                                const float* __restrict__ W) {
    int i = blockIdx.x * 256 + threadIdx.x;
    const float4* src;
    uint2* dst;
    int idx;
    if (i < XN4) { src = (const float4*)X; dst = (uint2*)g_xh; idx = i; }
    else if (i < XN4 + WN4) { src = (const float4*)W; dst = (uint2*)g_wh; idx = i - XN4; }
    else return;
    float4 v = src[idx];
    __half2 lo = __floats2half2_rn(v.x, v.y);
    __half2 hi = __floats2half2_rn(v.z, v.w);
    uint2 o;
    o.x = *(uint32_t*)&lo;
    o.y = *(uint32_t*)&hi;
    dst[idx] = o;
}

// ============================================================================
// fp16 mma.sync m16n8k16 GEMM + fused activations -> fp16 gate planes.
// CTA tile 128x128, 256 threads (8 warps: 4m x 2n), warp tile 32x64.
// 3-stage cp.async ring, ONE __syncthreads per iteration.
// ============================================================================
__global__ __launch_bounds__(256, 2) void gemm_mma(const float* __restrict__ bias) {
    extern __shared__ __half smem[];
    const uint32_t sb = smem_u32(smem);
    const int tid = threadIdx.x;
    const int wid = tid >> 5;
    const int lid = tid & 31;
    const int m0 = blockIdx.y * BM;
    const int n0 = blockIdx.x * BN;

    const int warp_m = (wid & 3) * 32;     // 0,32,64,96
    const int warp_n = (wid >> 2) * 64;    // 0,64

    const __half* Xb = g_xh + (size_t)m0 * KTOT;
    const __half* Wb = g_wh + (size_t)n0 * KTOT;

    float acc[2][8][4];
#pragma unroll
    for (int mf = 0; mf < 2; mf++)
#pragma unroll
        for (int nf = 0; nf < 8; nf++)
#pragma unroll
            for (int q = 0; q < 4; q++) acc[mf][nf][q] = 0.f;

    auto load_chunk = [&](int c, int s) {
        const uint32_t abase = sb + s * STG_BYTES;
        const uint32_t bbase = abase + A_BYTES;
        const int kc = c * BK;
#pragma unroll
        for (int p = 0; p < 2; p++) {
            int seg = tid + p * 256;           // 0..511
            int row = seg >> 2, ks = seg & 3;
            CP16(abase + row * (STRD * 2) + ks * 16,
                 Xb + (size_t)row * KTOT + kc + ks * 8);
        }
#pragma unroll
        for (int p = 0; p < 2; p++) {
            int seg = tid + p * 256;
            int row = seg >> 2, ks = seg & 3;
            CP16(bbase + row * (STRD * 2) + ks * 16,
                 Wb + (size_t)row * KTOT + kc + ks * 8);
        }
        asm volatile("cp.async.commit_group;" ::: "memory");
    };

    load_chunk(0, 0);
    load_chunk(1, 1);

    // ldmatrix per-thread addressing
    const int a_row  = lid & 15;
    const int a_byte = (lid >> 4) * 16;
    const int b_row  = (lid & 7) + 8 * (lid >> 4);
    const int b_byte = ((lid >> 3) & 1) * 16;

    for (int i = 0; i < NCHK; i++) {
        const int s = i % NSTG;
        if (i < NCHK - 2) asm volatile("cp.async.wait_group 1;" ::: "memory");
        else              asm volatile("cp.async.wait_group 0;" ::: "memory");
        __syncthreads();

        if (i + 2 < NCHK) load_chunk(i + 2, (i + 2) % NSTG);

        const uint32_t abase = sb + s * STG_BYTES;
        const uint32_t bbase = abase + A_BYTES;
        const uint32_t aaddr = abase + (warp_m + a_row) * (STRD * 2) + a_byte;
        const uint32_t baddr = bbase + (warp_n + b_row) * (STRD * 2) + b_byte;

#pragma unroll
        for (int ks2 = 0; ks2 < 2; ks2++) {
            const int kk = ks2 * 32;           // 16 halves = 32 bytes
            uint32_t af[2][4];
            ldsm4(af[0], aaddr + kk);
            ldsm4(af[1], aaddr + 16 * (STRD * 2) + kk);
            uint32_t bf[8][2];
#pragma unroll
            for (int np = 0; np < 4; np++)
                ldsm4(&bf[2 * np][0], baddr + np * 16 * (STRD * 2) + kk);
#pragma unroll
            for (int mf = 0; mf < 2; mf++)
#pragma unroll
                for (int nf = 0; nf < 8; nf++)
                    mma_f16(acc[mf][nf], af[mf], bf[nf]);
        }
    }

    // ---- epilogue: bias + activation, write fp16 gate plane ----
    const int lr = lid >> 2;
    const int lc = lid & 3;
    const int gate  = blockIdx.x >> 3;          // 8 x-blocks of 128 per gate
    const int hcol0 = (blockIdx.x & 7) * BN;
    __half* gout = g_gates + (size_t)gate * GSZ;

#pragma unroll
    for (int mf = 0; mf < 2; mf++) {
#pragma unroll
        for (int nf = 0; nf < 8; nf++) {
            const int ncol = warp_n + nf * 8 + 2 * lc;
            const float b0 = __ldg(&bias[n0 + ncol]);
            const float b1 = __ldg(&bias[n0 + ncol + 1]);
#pragma unroll
            for (int half_ = 0; half_ < 2; half_++) {
                const int m = m0 + warp_m + mf * 16 + lr + half_ * 8;
                float y0 = acc[mf][nf][2 * half_ + 0] + b0;
                float y1 = acc[mf][nf][2 * half_ + 1] + b1;
                float v0, v1;
                if (gate == 0) {
                    v0 = 2.f / (1.f + __expf(-2.f * y0)) - 1.f;  // tanh
                    v1 = 2.f / (1.f + __expf(-2.f * y1)) - 1.f;
                } else {
                    v0 = 1.f / (1.f + __expf(-y0));              // sigmoid
                    v1 = 1.f / (1.f + __expf(-y1));
                }
                *(__half2*)(gout + (size_t)m * HID + hcol0 + ncol) =
                    __floats2half2_rn(v0, v1);
            }
        }
    }
}

// ============================================================================
// Scan phase A: per-chunk affine composition (fp16 gates, 2 channels/thread).
// ============================================================================
__global__ __launch_bounds__(256) void scanA() {
    const int j2 = blockIdx.x * 256 + threadIdx.x;   // channel pair 0..4095
    const int ch = blockIdx.y;
    const __half2* Zp = (const __half2*)g_gates;
    const __half2* Fp = (const __half2*)(g_gates + GSZ);

    float2 A = make_float2(1.f, 1.f);
    float2 Bv = make_float2(0.f, 0.f);
    size_t base = (size_t)ch * TCH * BH2 + j2;
#pragma unroll 8
    for (int s = 0; s < TCH; s++) {
        size_t idx = base + (size_t)s * BH2;
        float2 f = __half22float2(Fp[idx]);
        float2 z = __half22float2(Zp[idx]);
        float ox = 1.f - f.x, oy = 1.f - f.y;
        A.x *= ox;                    A.y *= oy;
        Bv.x = f.x * z.x + ox * Bv.x; Bv.y = f.y * z.y + oy * Bv.y;
    }
    ((float2*)g_chA)[ch * BH2 + j2] = A;
    ((float2*)g_chB)[ch * BH2 + j2] = Bv;
}

// ============================================================================
// Scan phase B: sequential over 32 chunk states; records per-chunk carry.
// ============================================================================
__global__ __launch_bounds__(256) void scanB(const float* __restrict__ hidden,
                                             float* __restrict__ c_last) {
    const int j = blockIdx.x * 256 + threadIdx.x;
    float c = hidden[j];
#pragma unroll 8
    for (int i = 0; i < NCH; i++) {
        g_cin[i * BH + j] = c;
        c = g_chB[i * BH + j] + g_chA[i * BH + j] * c;
    }
    c_last[j] = c;
}

// ============================================================================
// Scan phase C: re-scan chunks with correct carries; write C and H (fp32).
// ============================================================================
__global__ __launch_bounds__(256) void scanC(float* __restrict__ Hout,
                                             float* __restrict__ Cout) {
    const int j2 = blockIdx.x * 256 + threadIdx.x;
    const int ch = blockIdx.y;
    const __half2* Zp = (const __half2*)g_gates;
    const __half2* Fp = (const __half2*)(g_gates + GSZ);
    const __half2* Gp = (const __half2*)(g_gates + 2 * GSZ);

    float2 c = ((const float2*)g_cin)[ch * BH2 + j2];
    size_t base = (size_t)ch * TCH * BH2 + j2;
#pragma unroll 4
    for (int s = 0; s < TCH; s++) {
        size_t idx = base + (size_t)s * BH2;
        float2 f = __half22float2(Fp[idx]);
        float2 z = __half22float2(Zp[idx]);
        float2 g = __half22float2(Gp[idx]);
        c.x = f.x * z.x + (1.f - f.x) * c.x;
        c.y = f.y * z.y + (1.f - f.y) * c.y;
        ((float2*)Cout)[idx] = c;
        ((float2*)Hout)[idx] = make_float2(g.x * c.x, g.y * c.y);
    }
}

// ============================================================================
// Launch: conv, noop, noop, gemm (ncu captures launch idx 3), scans.
// ============================================================================
extern "C" void kernel_launch(void* const* d_in, const int* in_sizes, int n_in,
                              void* d_out, int out_size) {
    const float* X      = (const float*)d_in[0];
    const float* hidden = (const float*)d_in[1];
    const float* W      = (const float*)d_in[2];
    const float* bias   = (const float*)d_in[3];

    float* out   = (float*)d_out;
    float* Hout  = out;
    float* Clast = out + GSZ;
    float* Cout  = out + GSZ + BH;

    cudaFuncSetAttribute(gemm_mma, cudaFuncAttributeMaxDynamicSharedMemorySize, SMEM_TOTAL);

    const int ctot = XN4 + WN4;
    conv_f16<<<(ctot + 255) / 256, 256>>>(X, W);
    noop_k<<<1, 32>>>();
    noop_k<<<1, 32>>>();
    gemm_mma<<<dim3(NTOT / BN, MTOT / BM), 256, SMEM_TOTAL>>>(bias);
    scanA<<<dim3(BH2 / 256, NCH), 256>>>();
    scanB<<<BH / 256, 256>>>(hidden, Clast);
    scanC<<<dim3(BH2 / 256, NCH), 256>>>(Hout, Cout);
}